// round 5
// baseline (speedup 1.0000x reference)
#include <cuda_runtime.h>

#define Fdim 64
#define Ldim 512
#define Bdim 256
#define HSZ  512
#define CAP  11      // max distinct count-values with precomputed rows

// ---------------------------------------------------------------------------
// Cold fallback: compute one table element from scratch (only if a block sees
// more than CAP distinct count values — never in practice, but keeps any
// input correct). tab: 0=feat(+bo/2), 1=q, 2=k, 3=v@Wo.
__device__ __noinline__ float cold_elem(int tab, int c, int d,
    const float* w1, const float* b1, const float* w2, const float* b2,
    const float* Wq, const float* Wk, const float* Wv, const float* Wo,
    const float* bo)
{
    if (tab == 0) {
        float acc = b2[d];
        for (int f = 0; f < 64; f++)
            acc += fmaxf((float)c * w1[f] + b1[f], 0.f) * w2[f * 64 + d];
        return acc + 0.5f * bo[d];
    }
    if (tab < 3) {
        const float* W = (tab == 1) ? Wq : Wk;
        float acc = 0.f;
        for (int g = 0; g < 64; g++) {
            float feat = b2[g];
            for (int f = 0; f < 64; f++)
                feat += fmaxf((float)c * w1[f] + b1[f], 0.f) * w2[f * 64 + g];
            acc += feat * W[g * 64 + d];
        }
        return acc;
    }
    float acc = 0.f;
    for (int e = 0; e < 64; e++) {
        float ve = 0.f;
        for (int g = 0; g < 64; g++) {
            float feat = b2[g];
            for (int f = 0; f < 64; f++)
                feat += fmaxf((float)c * w1[f] + b1[f], 0.f) * w2[f * 64 + g];
            ve += feat * Wv[g * 64 + e];
        }
        acc += ve * Wo[e * 64 + d];
    }
    return acc;
}

// Packed hash entry: (key << 10) | slot.  EMPTY = -1, PENDING slot = 0x3FF.
__device__ __forceinline__ int insert_pair(int key, int* tab, int* counter, int* keys)
{
    unsigned h = ((unsigned)key * 2654435761u) >> 23;   // 9-bit hash
    const int PEND = (key << 10) | 0x3FF;
    while (true) {
        int e = tab[h];
        if (e == -1) e = atomicCAS(&tab[h], -1, PEND);
        if (e == -1) {
            int s = atomicAdd(counter, 1);
            keys[s] = key;
            __threadfence_block();
            atomicExch(&tab[h], (key << 10) | s);
            return s;
        }
        if ((e >> 10) == key) {
            int s = e & 0x3FF;
            while (s == 0x3FF) s = ((volatile int*)tab)[h] & 0x3FF;
            return s;
        }
        h = (h + 1) & (HSZ - 1);
    }
}

// Shared plan (ints):
//  blob[3024]: phase1 = hist[2000] | hashA[512] | hashO[512]
//              phase2 = cslot u8[516] | rows float[CAP*4*64]
//  a_keys[512] o_keys[512] o_mult[512] counters[48] tok_as u16[512]
// floats: ctx2q[4096] Ebuf[2048] Vbuf[2048] colmax[64] part[256] cvec[128]
#define NINT (3024 + 3 * 512 + 48 + 256)
#define NFLT (4096 + 2048 + 2048 + 64 + 256 + 128)
#define SMEM_BYTES ((NINT + NFLT) * 4)

#define GETEL(s, tab, dd) (((s) < CAP) ? rows[((s) * 4 + (tab)) * 64 + (dd)] \
    : cold_elem((tab), (s) - CAP, (dd), w1, b1, w2, b2, Wq, Wk, Wv, Wo, bo))

__global__ void __launch_bounds__(256, 4) fused_kernel(
    const int* __restrict__ src, const int* __restrict__ dst,
    const float* __restrict__ w1, const float* __restrict__ b1,
    const float* __restrict__ w2, const float* __restrict__ b2,
    const float* __restrict__ Wq, const float* __restrict__ Wk,
    const float* __restrict__ Wv, const float* __restrict__ Wo,
    const float* __restrict__ bo,
    const float* __restrict__ lng, const float* __restrict__ lnb,
    float* __restrict__ out)
{
    extern __shared__ int sm[];
    int* blob     = sm;
    int* a_keys   = blob + 3024;
    int* o_keys   = a_keys + 512;
    int* o_mult   = o_keys + 512;
    int* counters = o_mult + 512;            // [0]=n_ap [1]=n_op [3]=n_cnt
    int* marks    = counters + 8;            // 17 ints bitmap over counts 0..512
    int* cvals    = counters + 25;           // [CAP] count value per slot
    unsigned short* tok_as = (unsigned short*)(counters + 48);
    float* ctx2q  = (float*)(counters + 48 + 256);
    float* Ebuf   = ctx2q + 4096;
    float* Vbuf   = Ebuf + 2048;
    float* colmax = Vbuf + 2048;
    float* part   = colmax + 64;
    float* cvec   = part + 256;
    // phase-1 aliases of blob
    int* hist  = blob;
    int* hashA = blob + 2000;
    int* hashO = hashA + HSZ;
    // phase-2 aliases of blob
    unsigned char* cslot = (unsigned char*)blob;          // 516 B
    float* rows = (float*)(blob + 129);                   // CAP*4*64 floats
    float* outrows = Ebuf;                                // 4096 (spans E+V)

    const int t = threadIdx.x;
    const int dir = blockIdx.x;
    const int b = blockIdx.y;
    const int* a_ids = (dir == 0 ? src : dst) + b * Ldim;
    const int* o_ids = (dir == 0 ? dst : src) + b * Ldim;

    // ---- init ----
    {
        int4* z = (int4*)hist;
        for (int i = t; i < 500; i += 256) z[i] = make_int4(0, 0, 0, 0);
        int4* hneg = (int4*)hashA;
        for (int i = t; i < 256; i += 256) hneg[i] = make_int4(-1, -1, -1, -1);
        int4* zm = (int4*)o_mult;
        for (int i = t; i < 128; i += 256) zm[i] = make_int4(0, 0, 0, 0);
    }
    if (t < 48) counters[t] = 0;
    if (t < 128) cvec[t] = (t < 64) ? lng[t] : lnb[t - 64];
    __syncthreads();

    // ---- packed histograms: a-count low16, o-count high16 ----
    const int av0 = a_ids[t], av1 = a_ids[t + 256];
    const int ov0 = o_ids[t], ov1 = o_ids[t + 256];
    atomicAdd(&hist[av0], 1);
    atomicAdd(&hist[av1], 1);
    atomicAdd(&hist[ov0], 1 << 16);
    atomicAdd(&hist[ov1], 1 << 16);
    __syncthreads();

    // ---- per-token count pairs -> dedupe ----
#pragma unroll
    for (int rep = 0; rep < 2; rep++) {
        const int l = t + rep * 256;
        const int av = rep ? av1 : av0, ov = rep ? ov1 : ov0;
        int ha = hist[av];
        int akey = av ? (((ha & 0xFFFF) << 10) | (ha >> 16)) : 0;
        tok_as[l] = (unsigned short)insert_pair(akey, hashA, &counters[0], a_keys);
        int ho = hist[ov];
        int okey = ov ? (((ho >> 16) << 10) | (ho & 0xFFFF)) : 0;
        int s = insert_pair(okey, hashO, &counters[1], o_keys);
        atomicAdd(&o_mult[s], 1);
    }
    __syncthreads();
    const int n_ap = counters[0], n_op = counters[1];

    // ---- mark needed count values ----
    for (int p = t; p < n_ap; p += 256) {
        int k = a_keys[p], i0 = k >> 10, i1 = k & 1023;
        atomicOr(&marks[i0 >> 5], 1u << (i0 & 31));
        atomicOr(&marks[i1 >> 5], 1u << (i1 & 31));
    }
    for (int p = t; p < n_op; p += 256) {
        int k = o_keys[p], i0 = k >> 10, i1 = k & 1023;
        atomicOr(&marks[i0 >> 5], 1u << (i0 & 31));
        atomicOr(&marks[i1 >> 5], 1u << (i1 & 31));
    }
    __syncthreads();
    // ---- assign slots (hist dead: cslot overlays blob start) ----
    for (int i = t; i <= 512; i += 256) {
        if (marks[i >> 5] & (1u << (i & 31))) {
            int s = atomicAdd(&counters[3], 1);
            cslot[i] = (s < CAP) ? (unsigned char)s : (unsigned char)0xFF;
            if (s < CAP) cvals[s] = i;
        }
    }
    __syncthreads();
    // ---- remap keys: counts -> slots (overflow keeps raw count) ----
    for (int p = t; p < n_ap; p += 256) {
        int k = a_keys[p], i0 = k >> 10, i1 = k & 1023;
        int s0 = (cslot[i0] != 0xFF) ? cslot[i0] : CAP + i0;
        int s1 = (cslot[i1] != 0xFF) ? cslot[i1] : CAP + i1;
        a_keys[p] = (s0 << 10) | s1;
    }
    for (int p = t; p < n_op; p += 256) {
        int k = o_keys[p], i0 = k >> 10, i1 = k & 1023;
        int s0 = (cslot[i0] != 0xFF) ? cslot[i0] : CAP + i0;
        int s1 = (cslot[i1] != 0xFF) ? cslot[i1] : CAP + i1;
        o_keys[p] = (s0 << 10) | s1;
    }
    __syncthreads();

    // ---- build table rows in smem for the needed counts ----
    const int nc = min(counters[3], CAP);
    const int nel = nc * 64;
    // stage A: r = relu(c*w1+b1)  -> Ebuf
    for (int idx = t; idx < nel; idx += 256) {
        int j = idx >> 6, f = idx & 63;
        Ebuf[idx] = fmaxf((float)cvals[j] * w1[f] + b1[f], 0.f);
    }
    __syncthreads();
    // stage B: feat = r@w2 + b2 -> Vbuf
    for (int idx = t; idx < nel; idx += 256) {
        int j = idx >> 6, g = idx & 63;
        float acc = b2[g];
#pragma unroll 8
        for (int f = 0; f < 64; f++) acc += Ebuf[j * 64 + f] * w2[f * 64 + g];
        Vbuf[idx] = acc;
    }
    __syncthreads();
    // stage C: feat(+bo/2), q=feat@Wq, k=feat@Wk, vtmp=feat@Wv (->Ebuf)
    for (int idx = t; idx < nel; idx += 256) {
        int j = idx >> 6, g = idx & 63;
        rows[(j * 4 + 0) * 64 + g] = Vbuf[idx] + 0.5f * bo[g];
        float aq = 0.f, ak = 0.f, av = 0.f;
#pragma unroll 8
        for (int f = 0; f < 64; f++) {
            float fe = Vbuf[j * 64 + f];
            aq += fe * Wq[f * 64 + g];
            ak += fe * Wk[f * 64 + g];
            av += fe * Wv[f * 64 + g];
        }
        rows[(j * 4 + 1) * 64 + g] = aq;
        rows[(j * 4 + 2) * 64 + g] = ak;
        Ebuf[idx] = av;
    }
    __syncthreads();
    // stage D: vWo = vtmp@Wo
    for (int idx = t; idx < nel; idx += 256) {
        int j = idx >> 6, g = idx & 63;
        float acc = 0.f;
#pragma unroll 8
        for (int f = 0; f < 64; f++) acc += Ebuf[j * 64 + f] * Wo[f * 64 + g];
        rows[(j * 4 + 3) * 64 + g] = acc;
    }
    __syncthreads();

    // ---- column max of K over unique o-pairs ----
    {
        const int d = t & 63, grp = t >> 6;
        float m = -3.4e38f;
        for (int p = grp; p < n_op; p += 4) {
            int key = o_keys[p], s0 = key >> 10, s1 = key & 1023;
            m = fmaxf(m, GETEL(s0, 2, d) + GETEL(s1, 2, d));
        }
        part[grp * 64 + d] = m;
    }
    __syncthreads();
    if (t < 64) {
        float m = part[t];
#pragma unroll
        for (int g = 1; g < 4; g++) m = fmaxf(m, part[g * 64 + t]);
        colmax[t] = m;
    }
    __syncthreads();

    // ---- Phase B: ctx2[d][g] = colinv[d] * sum_p E[p][d]*VWo[p][g] ----
    {
        const int dbase = (t >> 4) << 2, ebase = (t & 15) << 2;
        float acc[4][4] = {};
        float esum[4] = {};
        for (int pc = 0; pc < n_op; pc += 32) {
            const int cn = min(32, n_op - pc);
            for (int idx = t; idx < cn * 64; idx += 256) {
                int p = idx >> 6, d = idx & 63;
                int key = o_keys[pc + p], s0 = key >> 10, s1 = key & 1023;
                Ebuf[p * 64 + d] = (float)o_mult[pc + p] *
                    __expf(GETEL(s0, 2, d) + GETEL(s1, 2, d) - colmax[d]);
            }
            for (int idx = t; idx < cn * 64; idx += 256) {
                int p = idx >> 6, e = idx & 63;
                int key = o_keys[pc + p], s0 = key >> 10, s1 = key & 1023;
                Vbuf[p * 64 + e] = GETEL(s0, 3, e) + GETEL(s1, 3, e);
            }
            __syncthreads();
            for (int p = 0; p < cn; p++) {
                float4 ev = *(const float4*)&Ebuf[p * 64 + dbase];
                float4 vv = *(const float4*)&Vbuf[p * 64 + ebase];
                float e_[4] = {ev.x, ev.y, ev.z, ev.w};
                float v_[4] = {vv.x, vv.y, vv.z, vv.w};
#pragma unroll
                for (int i = 0; i < 4; i++)
#pragma unroll
                    for (int j = 0; j < 4; j++) acc[i][j] += e_[i] * v_[j];
                if (ebase == 0) {
#pragma unroll
                    for (int i = 0; i < 4; i++) esum[i] += e_[i];
                }
            }
            __syncthreads();
        }
        if (ebase == 0) {
#pragma unroll
            for (int i = 0; i < 4; i++) part[dbase + i] = esum[i];
        }
        __syncthreads();
        // float4-packed ctx2 layout: entry (d*32+e)*4 + comp,
        // comp: 0=(d,e) 1=(d,e+32) 2=(d+32,e) 3=(d+32,e+32), d,e in 0..31
        const int dd = dbase & 31, hi = (dbase >> 5) << 1;
        const int el = ebase & 31, eh = ebase >> 5;
#pragma unroll
        for (int i = 0; i < 4; i++) {
            float inv = 1.0f / part[dbase + i];
#pragma unroll
            for (int j = 0; j < 4; j++)
                ctx2q[((dd + i) * 32 + el + j) * 4 + hi + eh] = acc[i][j] * inv;
        }
    }
    __syncthreads();

    // ---- Phase C: 2 a-pairs per warp pass; softmax->attn->LN; scatter ----
    {
        const int w = t >> 5, lane = t & 31;
        const float g0 = cvec[lane], g1 = cvec[32 + lane];
        const float be0 = cvec[64 + lane], be1 = cvec[96 + lane];
        const size_t outbase = (((size_t)dir * Bdim + b) * Ldim) * 64;

        for (int ac = 0; ac < n_ap; ac += 64) {
            const int an = min(64, n_ap - ac);
            for (int p = w * 2; p < an; p += 16) {
                const bool has2 = (p + 1 < an);
                int keyA = a_keys[ac + p];
                int keyB = a_keys[ac + (has2 ? p + 1 : p)];
                int A0 = keyA >> 10, A1 = keyA & 1023;
                int B0 = keyB >> 10, B1 = keyB & 1023;
                float qA0 = GETEL(A0, 1, lane) + GETEL(A1, 1, lane);
                float qA1 = GETEL(A0, 1, 32 + lane) + GETEL(A1, 1, 32 + lane);
                float fA0 = GETEL(A0, 0, lane) + GETEL(A1, 0, lane);
                float fA1 = GETEL(A0, 0, 32 + lane) + GETEL(A1, 0, 32 + lane);
                float qB0 = GETEL(B0, 1, lane) + GETEL(B1, 1, lane);
                float qB1 = GETEL(B0, 1, 32 + lane) + GETEL(B1, 1, 32 + lane);
                float fB0 = GETEL(B0, 0, lane) + GETEL(B1, 0, lane);
                float fB1 = GETEL(B0, 0, 32 + lane) + GETEL(B1, 0, 32 + lane);
                float mA = fmaxf(qA0, qA1), mB = fmaxf(qB0, qB1);
#pragma unroll
                for (int off = 16; off; off >>= 1) {
                    mA = fmaxf(mA, __shfl_xor_sync(~0u, mA, off));
                    mB = fmaxf(mB, __shfl_xor_sync(~0u, mB, off));
                }
                float eA0 = __expf(qA0 - mA), eA1 = __expf(qA1 - mA);
                float eB0 = __expf(qB0 - mB), eB1 = __expf(qB1 - mB);
                float sA = eA0 + eA1, sB = eB0 + eB1;
#pragma unroll
                for (int off = 16; off; off >>= 1) {
                    sA += __shfl_xor_sync(~0u, sA, off);
                    sB += __shfl_xor_sync(~0u, sB, off);
                }
                float cA = 0.125f / sA, cB = 0.125f / sB;
                eA0 *= cA; eA1 *= cA; eB0 *= cB; eB1 *= cB;
                float a0A = 0.f, a1A = 0.f, a0B = 0.f, a1B = 0.f;
#pragma unroll 8
                for (int d = 0; d < 32; d++) {
                    float qloA = __shfl_sync(~0u, eA0, d);
                    float qhiA = __shfl_sync(~0u, eA1, d);
                    float qloB = __shfl_sync(~0u, eB0, d);
                    float qhiB = __shfl_sync(~0u, eB1, d);
                    float4 cp = *(const float4*)&ctx2q[(d * 32 + lane) * 4];
                    a0A += qloA * cp.x + qhiA * cp.z;
                    a1A += qloA * cp.y + qhiA * cp.w;
                    a0B += qloB * cp.x + qhiB * cp.z;
                    a1B += qloB * cp.y + qhiB * cp.w;
                }
                float y0A = fA0 + a0A, y1A = fA1 + a1A;
                float y0B = fB0 + a0B, y1B = fB1 + a1B;
                float muA = y0A + y1A, muB = y0B + y1B;
#pragma unroll
                for (int off = 16; off; off >>= 1) {
                    muA += __shfl_xor_sync(~0u, muA, off);
                    muB += __shfl_xor_sync(~0u, muB, off);
                }
                muA *= (1.0f / 64.0f); muB *= (1.0f / 64.0f);
                float d0A = y0A - muA, d1A = y1A - muA;
                float d0B = y0B - muB, d1B = y1B - muB;
                float vA = d0A * d0A + d1A * d1A;
                float vB = d0B * d0B + d1B * d1B;
#pragma unroll
                for (int off = 16; off; off >>= 1) {
                    vA += __shfl_xor_sync(~0u, vA, off);
                    vB += __shfl_xor_sync(~0u, vB, off);
                }
                float rsA = rsqrtf(vA * (1.0f / 64.0f) + 1e-5f);
                float rsB = rsqrtf(vB * (1.0f / 64.0f) + 1e-5f);
                outrows[p * 64 + lane]      = d0A * rsA * g0 + be0;
                outrows[p * 64 + 32 + lane] = d1A * rsA * g1 + be1;
                if (has2) {
                    outrows[(p + 1) * 64 + lane]      = d0B * rsB * g0 + be0;
                    outrows[(p + 1) * 64 + 32 + lane] = d1B * rsB * g1 + be1;
                }
            }
            __syncthreads();
            {
                const int half = lane >> 4, q = lane & 15;
                for (int l = w * 2 + half; l < Ldim; l += 16) {
                    int s = (int)tok_as[l] - ac;
                    if ((unsigned)s < (unsigned)an) {
                        float4 v = *(const float4*)&outrows[s * 64 + q * 4];
                        *(float4*)&out[outbase + (size_t)l * 64 + q * 4] = v;
                    }
                }
            }
            __syncthreads();
        }
    }
}

// ---------------------------------------------------------------------------
extern "C" void kernel_launch(void* const* d_in, const int* in_sizes, int n_in,
                              void* d_out, int out_size)
{
    const int*   src = (const int*)d_in[0];
    const int*   dst = (const int*)d_in[1];
    const float* w1  = (const float*)d_in[2];
    const float* b1  = (const float*)d_in[3];
    const float* w2  = (const float*)d_in[4];
    const float* b2  = (const float*)d_in[5];
    const float* Wq  = (const float*)d_in[6];
    const float* Wk  = (const float*)d_in[7];
    const float* Wv  = (const float*)d_in[8];
    const float* Wo  = (const float*)d_in[9];
    const float* bo  = (const float*)d_in[10];
    const float* lng = (const float*)d_in[11];
    const float* lnb = (const float*)d_in[12];
    float* out = (float*)d_out;

    cudaFuncSetAttribute(fused_kernel, cudaFuncAttributeMaxDynamicSharedMemorySize, SMEM_BYTES);
    fused_kernel<<<dim3(2, Bdim), 256, SMEM_BYTES>>>(
        src, dst, w1, b1, w2, b2, Wq, Wk, Wv, Wo, bo, lng, lnb, out);
}